// round 15
// baseline (speedup 1.0000x reference)
#include <cuda_runtime.h>
#include <math.h>

#define NTHREADS 128
#define OPT 8                       // outputs per thread
#define TILE (NTHREADS * OPT)       // 1024 samples per block
#define NTAPS 5
#define NSAMP 131072
#define BATCH 64
#define FS_F 30720000.0f
#define SCS_F 15000.0f
#define MAX_CFO_F 0.05f
#define TWO_PI_F 6.28318530717958647692f

__global__ __launch_bounds__(NTHREADS, 12)
void wireless_channel_kernel(
    const float* __restrict__ x_real,  const float* __restrict__ x_imag,
    const float* __restrict__ ebno_db, const float* __restrict__ cfo_u,
    const float* __restrict__ taps_real, const float* __restrict__ taps_imag,
    const float* __restrict__ noise_real, const float* __restrict__ noise_imag,
    float* __restrict__ out)
{
    const int b    = blockIdx.y;
    const int n0   = blockIdx.x * TILE + threadIdx.x * OPT;  // first output sample
    const int lane = threadIdx.x & 31;

    const float* __restrict__ xr_row = x_real + (size_t)b * NSAMP;
    const float* __restrict__ xi_row = x_imag + (size_t)b * NSAMP;

    // ---- own 8 samples, exactly aligned: 2x LDG.128 per array ----
    float4 xr4a = ((const float4*)(xr_row + n0))[0];
    float4 xr4b = ((const float4*)(xr_row + n0))[1];
    float4 xi4a = ((const float4*)(xi_row + n0))[0];
    float4 xi4b = ((const float4*)(xi_row + n0))[1];

    // ---- per-row scalars (broadcast loads) ----
    const float cfo    = cfo_u[b];
    const float deltaf = (cfo * 2.0f - 1.0f) * MAX_CFO_F * SCS_F;
    const float w      = (TWO_PI_F * deltaf) / FS_F;          // rad / sample
    const float snr    = ebno_db[b] + 1.7609125905568124f;    // +10*log10(1.5)
    const float scale  = 0.5f * exp2f(-snr * 0.16609640474436813f); // 10^(-snr/20)

    float tr[NTAPS], ti[NTAPS];
    #pragma unroll
    for (int k = 0; k < NTAPS; k++) {
        tr[k] = taps_real[b * NTAPS + k];
        ti[k] = taps_imag[b * NTAPS + k];
    }

    // ---- CFO rotation of own 8 samples via phase recurrence ----
    float rxr[OPT], rxi[OPT];
    float s0, c0, sw, cw;
    __sincosf(w * (float)n0, &s0, &c0);       // phase at first own sample
    __sincosf(w, &sw, &cw);                   // per-sample rotation step

    float xrl[OPT] = { xr4a.x, xr4a.y, xr4a.z, xr4a.w, xr4b.x, xr4b.y, xr4b.z, xr4b.w };
    float xil[OPT] = { xi4a.x, xi4a.y, xi4a.z, xi4a.w, xi4b.x, xi4b.y, xi4b.z, xi4b.w };

    float s = s0, c = c0;
    #pragma unroll
    for (int i = 0; i < OPT; i++) {
        rxr[i] = xrl[i] * c - xil[i] * s;
        rxi[i] = xrl[i] * s + xil[i] * c;
        const float c2 = c * cw - s * sw;     // advance phase by w
        const float s2 = c * sw + s * cw;
        c = c2; s = s2;
    }
    // (s, c) now holds phase at sample n0 + 8

    // ---- halos via lane shuffles of rotated values ----
    const unsigned FULL = 0xFFFFFFFFu;
    float lr0 = __shfl_up_sync(FULL, rxr[6], 1);   // rotated x[n0-2]
    float lr1 = __shfl_up_sync(FULL, rxr[7], 1);   // rotated x[n0-1]
    float li0 = __shfl_up_sync(FULL, rxi[6], 1);
    float li1 = __shfl_up_sync(FULL, rxi[7], 1);
    float rr0 = __shfl_down_sync(FULL, rxr[0], 1); // rotated x[n0+8]
    float rr1 = __shfl_down_sync(FULL, rxr[1], 1); // rotated x[n0+9]
    float ri0 = __shfl_down_sync(FULL, rxi[0], 1);
    float ri1 = __shfl_down_sync(FULL, rxi[1], 1);

    // warp-edge lanes patch their halo with scalar loads + local phase rotation
    if (lane == 0) {
        // back-rotate phase from n0 to n0-1, n0-2
        const float cm1 = c0 * cw + s0 * sw;
        const float sm1 = s0 * cw - c0 * sw;      // phase (n0-1)
        const float cm2 = cm1 * cw + sm1 * sw;
        const float sm2 = sm1 * cw - cm1 * sw;    // phase (n0-2)
        float xrm2 = 0.0f, xim2 = 0.0f, xrm1 = 0.0f, xim1 = 0.0f;
        if (n0 - 2 >= 0) { xrm2 = xr_row[n0 - 2]; xim2 = xi_row[n0 - 2]; }
        if (n0 - 1 >= 0) { xrm1 = xr_row[n0 - 1]; xim1 = xi_row[n0 - 1]; }
        lr0 = xrm2 * cm2 - xim2 * sm2;
        li0 = xrm2 * sm2 + xim2 * cm2;
        lr1 = xrm1 * cm1 - xim1 * sm1;
        li1 = xrm1 * sm1 + xim1 * cm1;
    }
    if (lane == 31) {
        // (s, c) = phase at n0+8; advance once for n0+9
        const float cp1 = c * cw - s * sw;
        const float sp1 = c * sw + s * cw;
        float xr8 = 0.0f, xi8 = 0.0f, xr9 = 0.0f, xi9 = 0.0f;
        if (n0 + 8 < NSAMP) { xr8 = xr_row[n0 + 8]; xi8 = xi_row[n0 + 8]; }
        if (n0 + 9 < NSAMP) { xr9 = xr_row[n0 + 9]; xi9 = xi_row[n0 + 9]; }
        rr0 = xr8 * c - xi8 * s;
        ri0 = xr8 * s + xi8 * c;
        rr1 = xr9 * cp1 - xi9 * sp1;
        ri1 = xr9 * sp1 + xi9 * cp1;
    }

    // ---- assemble 12-sample rotated window [n0-2, n0+9] ----
    float wr[OPT + 4], wi[OPT + 4];
    wr[0] = lr0; wr[1] = lr1; wi[0] = li0; wi[1] = li1;
    #pragma unroll
    for (int i = 0; i < OPT; i++) { wr[i + 2] = rxr[i]; wi[i + 2] = rxi[i]; }
    wr[10] = rr0; wr[11] = rr1; wi[10] = ri0; wi[11] = ri1;

    // ---- noise (vectorized) ----
    const float4* __restrict__ nr4 = (const float4*)(noise_real + (size_t)b * NSAMP + n0);
    const float4* __restrict__ ni4 = (const float4*)(noise_imag + (size_t)b * NSAMP + n0);
    float4 nr[2] = { nr4[0], nr4[1] };
    float4 ni[2] = { ni4[0], ni4[1] };
    const float* nrp = (const float*)nr;
    const float* nip = (const float*)ni;

    // ---- 5-tap complex conv + AWGN ----
    float yr[OPT], yi[OPT];
    #pragma unroll
    for (int j = 0; j < OPT; j++) {
        float s_rr = 0.0f, s_ii = 0.0f, s_ri = 0.0f, s_ir = 0.0f;
        #pragma unroll
        for (int k = 0; k < NTAPS; k++) {
            s_rr = fmaf(tr[k], wr[j + k], s_rr);
            s_ii = fmaf(ti[k], wi[j + k], s_ii);
            s_ir = fmaf(ti[k], wr[j + k], s_ir);
            s_ri = fmaf(tr[k], wi[j + k], s_ri);
        }
        yr[j] = (s_rr - s_ii) + nrp[j] * scale;
        yi[j] = (s_ir + s_ri) + nip[j] * scale;
    }

    // ---- streaming stores (write-once data, evict-first): out[0]=real, out[1]=imag ----
    float4* outr = (float4*)(out + (size_t)b * NSAMP + n0);
    float4* outi = (float4*)(out + (size_t)BATCH * NSAMP + (size_t)b * NSAMP + n0);
    __stcs(outr + 0, make_float4(yr[0], yr[1], yr[2], yr[3]));
    __stcs(outr + 1, make_float4(yr[4], yr[5], yr[6], yr[7]));
    __stcs(outi + 0, make_float4(yi[0], yi[1], yi[2], yi[3]));
    __stcs(outi + 1, make_float4(yi[4], yi[5], yi[6], yi[7]));
}

extern "C" void kernel_launch(void* const* d_in, const int* in_sizes, int n_in,
                              void* d_out, int out_size)
{
    const float* x_real     = (const float*)d_in[0];
    const float* x_imag     = (const float*)d_in[1];
    const float* ebno_db    = (const float*)d_in[2];
    const float* cfo_u      = (const float*)d_in[3];
    const float* taps_real  = (const float*)d_in[4];
    const float* taps_imag  = (const float*)d_in[5];
    const float* noise_real = (const float*)d_in[6];
    const float* noise_imag = (const float*)d_in[7];
    float* out = (float*)d_out;

    dim3 grid(NSAMP / TILE, BATCH);   // (128, 64)
    wireless_channel_kernel<<<grid, NTHREADS>>>(
        x_real, x_imag, ebno_db, cfo_u, taps_real, taps_imag,
        noise_real, noise_imag, out);
}

// round 16
// speedup vs baseline: 1.0481x; 1.0481x over previous
#include <cuda_runtime.h>
#include <math.h>

#define NTHREADS 128
#define OPT 8                       // outputs per thread
#define TILE (NTHREADS * OPT)       // 1024 samples per block
#define NTAPS 5
#define NSAMP 131072
#define BATCH 64
#define FS_F 30720000.0f
#define SCS_F 15000.0f
#define MAX_CFO_F 0.05f
#define TWO_PI_F 6.28318530717958647692f

__global__ __launch_bounds__(NTHREADS, 12)
void wireless_channel_kernel(
    const float* __restrict__ x_real,  const float* __restrict__ x_imag,
    const float* __restrict__ ebno_db, const float* __restrict__ cfo_u,
    const float* __restrict__ taps_real, const float* __restrict__ taps_imag,
    const float* __restrict__ noise_real, const float* __restrict__ noise_imag,
    float* __restrict__ out)
{
    const int b    = blockIdx.y;
    const int n0   = blockIdx.x * TILE + threadIdx.x * OPT;  // first output sample
    const int lane = threadIdx.x & 31;

    const float* __restrict__ xr_row = x_real + (size_t)b * NSAMP;
    const float* __restrict__ xi_row = x_imag + (size_t)b * NSAMP;

    // ---- own 8 samples, exactly aligned: 2x LDG.128 per array ----
    float4 xr4a = ((const float4*)(xr_row + n0))[0];
    float4 xr4b = ((const float4*)(xr_row + n0))[1];
    float4 xi4a = ((const float4*)(xi_row + n0))[0];
    float4 xi4b = ((const float4*)(xi_row + n0))[1];

    // ---- per-row scalars (broadcast loads) ----
    const float cfo    = cfo_u[b];
    const float deltaf = (cfo * 2.0f - 1.0f) * MAX_CFO_F * SCS_F;
    const float w      = (TWO_PI_F * deltaf) / FS_F;          // rad / sample
    const float snr    = ebno_db[b] + 1.7609125905568124f;    // +10*log10(1.5)
    const float scale  = 0.5f * exp2f(-snr * 0.16609640474436813f); // 10^(-snr/20)

    float tr[NTAPS], ti[NTAPS];
    #pragma unroll
    for (int k = 0; k < NTAPS; k++) {
        tr[k] = taps_real[b * NTAPS + k];
        ti[k] = taps_imag[b * NTAPS + k];
    }

    // ---- CFO rotation of own 8 samples via phase recurrence ----
    float rxr[OPT], rxi[OPT];
    float s0, c0, sw, cw;
    __sincosf(w * (float)n0, &s0, &c0);       // phase at first own sample
    __sincosf(w, &sw, &cw);                   // per-sample rotation step

    float xrl[OPT] = { xr4a.x, xr4a.y, xr4a.z, xr4a.w, xr4b.x, xr4b.y, xr4b.z, xr4b.w };
    float xil[OPT] = { xi4a.x, xi4a.y, xi4a.z, xi4a.w, xi4b.x, xi4b.y, xi4b.z, xi4b.w };

    float s = s0, c = c0;
    #pragma unroll
    for (int i = 0; i < OPT; i++) {
        rxr[i] = xrl[i] * c - xil[i] * s;
        rxi[i] = xrl[i] * s + xil[i] * c;
        const float c2 = c * cw - s * sw;     // advance phase by w
        const float s2 = c * sw + s * cw;
        c = c2; s = s2;
    }
    // (s, c) now holds phase at sample n0 + 8

    // ---- halos via lane shuffles of rotated values ----
    const unsigned FULL = 0xFFFFFFFFu;
    float lr0 = __shfl_up_sync(FULL, rxr[6], 1);   // rotated x[n0-2]
    float lr1 = __shfl_up_sync(FULL, rxr[7], 1);   // rotated x[n0-1]
    float li0 = __shfl_up_sync(FULL, rxi[6], 1);
    float li1 = __shfl_up_sync(FULL, rxi[7], 1);
    float rr0 = __shfl_down_sync(FULL, rxr[0], 1); // rotated x[n0+8]
    float rr1 = __shfl_down_sync(FULL, rxr[1], 1); // rotated x[n0+9]
    float ri0 = __shfl_down_sync(FULL, rxi[0], 1);
    float ri1 = __shfl_down_sync(FULL, rxi[1], 1);

    // warp-edge lanes patch their halo with scalar loads + local phase rotation
    if (lane == 0) {
        // back-rotate phase from n0 to n0-1, n0-2
        const float cm1 = c0 * cw + s0 * sw;
        const float sm1 = s0 * cw - c0 * sw;      // phase (n0-1)
        const float cm2 = cm1 * cw + sm1 * sw;
        const float sm2 = sm1 * cw - cm1 * sw;    // phase (n0-2)
        float xrm2 = 0.0f, xim2 = 0.0f, xrm1 = 0.0f, xim1 = 0.0f;
        if (n0 - 2 >= 0) { xrm2 = xr_row[n0 - 2]; xim2 = xi_row[n0 - 2]; }
        if (n0 - 1 >= 0) { xrm1 = xr_row[n0 - 1]; xim1 = xi_row[n0 - 1]; }
        lr0 = xrm2 * cm2 - xim2 * sm2;
        li0 = xrm2 * sm2 + xim2 * cm2;
        lr1 = xrm1 * cm1 - xim1 * sm1;
        li1 = xrm1 * sm1 + xim1 * cm1;
    }
    if (lane == 31) {
        // (s, c) = phase at n0+8; advance once for n0+9
        const float cp1 = c * cw - s * sw;
        const float sp1 = c * sw + s * cw;
        float xr8 = 0.0f, xi8 = 0.0f, xr9 = 0.0f, xi9 = 0.0f;
        if (n0 + 8 < NSAMP) { xr8 = xr_row[n0 + 8]; xi8 = xi_row[n0 + 8]; }
        if (n0 + 9 < NSAMP) { xr9 = xr_row[n0 + 9]; xi9 = xi_row[n0 + 9]; }
        rr0 = xr8 * c - xi8 * s;
        ri0 = xr8 * s + xi8 * c;
        rr1 = xr9 * cp1 - xi9 * sp1;
        ri1 = xr9 * sp1 + xi9 * cp1;
    }

    // ---- assemble 12-sample rotated window [n0-2, n0+9] ----
    float wr[OPT + 4], wi[OPT + 4];
    wr[0] = lr0; wr[1] = lr1; wi[0] = li0; wi[1] = li1;
    #pragma unroll
    for (int i = 0; i < OPT; i++) { wr[i + 2] = rxr[i]; wi[i + 2] = rxi[i]; }
    wr[10] = rr0; wr[11] = rr1; wi[10] = ri0; wi[11] = ri1;

    // ---- noise (read-once: streaming loads, evict-first) ----
    const float4* __restrict__ nr4 = (const float4*)(noise_real + (size_t)b * NSAMP + n0);
    const float4* __restrict__ ni4 = (const float4*)(noise_imag + (size_t)b * NSAMP + n0);
    float4 nr[2] = { __ldcs(nr4 + 0), __ldcs(nr4 + 1) };
    float4 ni[2] = { __ldcs(ni4 + 0), __ldcs(ni4 + 1) };
    const float* nrp = (const float*)nr;
    const float* nip = (const float*)ni;

    // ---- 5-tap complex conv + AWGN ----
    float yr[OPT], yi[OPT];
    #pragma unroll
    for (int j = 0; j < OPT; j++) {
        float s_rr = 0.0f, s_ii = 0.0f, s_ri = 0.0f, s_ir = 0.0f;
        #pragma unroll
        for (int k = 0; k < NTAPS; k++) {
            s_rr = fmaf(tr[k], wr[j + k], s_rr);
            s_ii = fmaf(ti[k], wi[j + k], s_ii);
            s_ir = fmaf(ti[k], wr[j + k], s_ir);
            s_ri = fmaf(tr[k], wi[j + k], s_ri);
        }
        yr[j] = (s_rr - s_ii) + nrp[j] * scale;
        yi[j] = (s_ir + s_ri) + nip[j] * scale;
    }

    // ---- streaming stores (write-once data, evict-first): out[0]=real, out[1]=imag ----
    float4* outr = (float4*)(out + (size_t)b * NSAMP + n0);
    float4* outi = (float4*)(out + (size_t)BATCH * NSAMP + (size_t)b * NSAMP + n0);
    __stcs(outr + 0, make_float4(yr[0], yr[1], yr[2], yr[3]));
    __stcs(outr + 1, make_float4(yr[4], yr[5], yr[6], yr[7]));
    __stcs(outi + 0, make_float4(yi[0], yi[1], yi[2], yi[3]));
    __stcs(outi + 1, make_float4(yi[4], yi[5], yi[6], yi[7]));
}

extern "C" void kernel_launch(void* const* d_in, const int* in_sizes, int n_in,
                              void* d_out, int out_size)
{
    const float* x_real     = (const float*)d_in[0];
    const float* x_imag     = (const float*)d_in[1];
    const float* ebno_db    = (const float*)d_in[2];
    const float* cfo_u      = (const float*)d_in[3];
    const float* taps_real  = (const float*)d_in[4];
    const float* taps_imag  = (const float*)d_in[5];
    const float* noise_real = (const float*)d_in[6];
    const float* noise_imag = (const float*)d_in[7];
    float* out = (float*)d_out;

    dim3 grid(NSAMP / TILE, BATCH);   // (128, 64)
    wireless_channel_kernel<<<grid, NTHREADS>>>(
        x_real, x_imag, ebno_db, cfo_u, taps_real, taps_imag,
        noise_real, noise_imag, out);
}

// round 17
// speedup vs baseline: 1.1179x; 1.0667x over previous
#include <cuda_runtime.h>
#include <math.h>

#define NTHREADS 128
#define OPT 8                       // outputs per thread
#define TILE (NTHREADS * OPT)       // 1024 samples per block
#define NTAPS 5
#define NSAMP 131072
#define BATCH 64
#define FS_F 30720000.0f
#define SCS_F 15000.0f
#define MAX_CFO_F 0.05f
#define TWO_PI_F 6.28318530717958647692f

__global__ __launch_bounds__(NTHREADS, 12)
void wireless_channel_kernel(
    const float* __restrict__ x_real,  const float* __restrict__ x_imag,
    const float* __restrict__ ebno_db, const float* __restrict__ cfo_u,
    const float* __restrict__ taps_real, const float* __restrict__ taps_imag,
    const float* __restrict__ noise_real, const float* __restrict__ noise_imag,
    float* __restrict__ out)
{
    const int b    = blockIdx.y;
    const int n0   = blockIdx.x * TILE + threadIdx.x * OPT;  // first output sample
    const int lane = threadIdx.x & 31;

    const float* __restrict__ xr_row = x_real + (size_t)b * NSAMP;
    const float* __restrict__ xi_row = x_imag + (size_t)b * NSAMP;

    // ---- own 8 samples, exactly aligned: 2x LDG.128 per array (streaming) ----
    const float4* xr4p = (const float4*)(xr_row + n0);
    const float4* xi4p = (const float4*)(xi_row + n0);
    float4 xr4a = __ldcs(xr4p + 0);
    float4 xr4b = __ldcs(xr4p + 1);
    float4 xi4a = __ldcs(xi4p + 0);
    float4 xi4b = __ldcs(xi4p + 1);

    // ---- per-row scalars (broadcast loads) ----
    const float cfo    = cfo_u[b];
    const float deltaf = (cfo * 2.0f - 1.0f) * MAX_CFO_F * SCS_F;
    const float w      = (TWO_PI_F * deltaf) / FS_F;          // rad / sample
    const float snr    = ebno_db[b] + 1.7609125905568124f;    // +10*log10(1.5)
    const float scale  = 0.5f * exp2f(-snr * 0.16609640474436813f); // 10^(-snr/20)

    float tr[NTAPS], ti[NTAPS];
    #pragma unroll
    for (int k = 0; k < NTAPS; k++) {
        tr[k] = taps_real[b * NTAPS + k];
        ti[k] = taps_imag[b * NTAPS + k];
    }

    // ---- CFO rotation of own 8 samples via phase recurrence ----
    float rxr[OPT], rxi[OPT];
    float s0, c0, sw, cw;
    __sincosf(w * (float)n0, &s0, &c0);       // phase at first own sample
    __sincosf(w, &sw, &cw);                   // per-sample rotation step

    float xrl[OPT] = { xr4a.x, xr4a.y, xr4a.z, xr4a.w, xr4b.x, xr4b.y, xr4b.z, xr4b.w };
    float xil[OPT] = { xi4a.x, xi4a.y, xi4a.z, xi4a.w, xi4b.x, xi4b.y, xi4b.z, xi4b.w };

    float s = s0, c = c0;
    #pragma unroll
    for (int i = 0; i < OPT; i++) {
        rxr[i] = xrl[i] * c - xil[i] * s;
        rxi[i] = xrl[i] * s + xil[i] * c;
        const float c2 = c * cw - s * sw;     // advance phase by w
        const float s2 = c * sw + s * cw;
        c = c2; s = s2;
    }
    // (s, c) now holds phase at sample n0 + 8

    // ---- halos via lane shuffles of rotated values ----
    const unsigned FULL = 0xFFFFFFFFu;
    float lr0 = __shfl_up_sync(FULL, rxr[6], 1);   // rotated x[n0-2]
    float lr1 = __shfl_up_sync(FULL, rxr[7], 1);   // rotated x[n0-1]
    float li0 = __shfl_up_sync(FULL, rxi[6], 1);
    float li1 = __shfl_up_sync(FULL, rxi[7], 1);
    float rr0 = __shfl_down_sync(FULL, rxr[0], 1); // rotated x[n0+8]
    float rr1 = __shfl_down_sync(FULL, rxr[1], 1); // rotated x[n0+9]
    float ri0 = __shfl_down_sync(FULL, rxi[0], 1);
    float ri1 = __shfl_down_sync(FULL, rxi[1], 1);

    // warp-edge lanes patch their halo with scalar loads + local phase rotation
    if (lane == 0) {
        // back-rotate phase from n0 to n0-1, n0-2
        const float cm1 = c0 * cw + s0 * sw;
        const float sm1 = s0 * cw - c0 * sw;      // phase (n0-1)
        const float cm2 = cm1 * cw + sm1 * sw;
        const float sm2 = sm1 * cw - cm1 * sw;    // phase (n0-2)
        float xrm2 = 0.0f, xim2 = 0.0f, xrm1 = 0.0f, xim1 = 0.0f;
        if (n0 - 2 >= 0) { xrm2 = xr_row[n0 - 2]; xim2 = xi_row[n0 - 2]; }
        if (n0 - 1 >= 0) { xrm1 = xr_row[n0 - 1]; xim1 = xi_row[n0 - 1]; }
        lr0 = xrm2 * cm2 - xim2 * sm2;
        li0 = xrm2 * sm2 + xim2 * cm2;
        lr1 = xrm1 * cm1 - xim1 * sm1;
        li1 = xrm1 * sm1 + xim1 * cm1;
    }
    if (lane == 31) {
        // (s, c) = phase at n0+8; advance once for n0+9
        const float cp1 = c * cw - s * sw;
        const float sp1 = c * sw + s * cw;
        float xr8 = 0.0f, xi8 = 0.0f, xr9 = 0.0f, xi9 = 0.0f;
        if (n0 + 8 < NSAMP) { xr8 = xr_row[n0 + 8]; xi8 = xi_row[n0 + 8]; }
        if (n0 + 9 < NSAMP) { xr9 = xr_row[n0 + 9]; xi9 = xi_row[n0 + 9]; }
        rr0 = xr8 * c - xi8 * s;
        ri0 = xr8 * s + xi8 * c;
        rr1 = xr9 * cp1 - xi9 * sp1;
        ri1 = xr9 * sp1 + xi9 * cp1;
    }

    // ---- assemble 12-sample rotated window [n0-2, n0+9] ----
    float wr[OPT + 4], wi[OPT + 4];
    wr[0] = lr0; wr[1] = lr1; wi[0] = li0; wi[1] = li1;
    #pragma unroll
    for (int i = 0; i < OPT; i++) { wr[i + 2] = rxr[i]; wi[i + 2] = rxi[i]; }
    wr[10] = rr0; wr[11] = rr1; wi[10] = ri0; wi[11] = ri1;

    // ---- noise (read-once: streaming loads, evict-first) ----
    const float4* __restrict__ nr4 = (const float4*)(noise_real + (size_t)b * NSAMP + n0);
    const float4* __restrict__ ni4 = (const float4*)(noise_imag + (size_t)b * NSAMP + n0);
    float4 nr[2] = { __ldcs(nr4 + 0), __ldcs(nr4 + 1) };
    float4 ni[2] = { __ldcs(ni4 + 0), __ldcs(ni4 + 1) };
    const float* nrp = (const float*)nr;
    const float* nip = (const float*)ni;

    // ---- 5-tap complex conv + AWGN ----
    float yr[OPT], yi[OPT];
    #pragma unroll
    for (int j = 0; j < OPT; j++) {
        float s_rr = 0.0f, s_ii = 0.0f, s_ri = 0.0f, s_ir = 0.0f;
        #pragma unroll
        for (int k = 0; k < NTAPS; k++) {
            s_rr = fmaf(tr[k], wr[j + k], s_rr);
            s_ii = fmaf(ti[k], wi[j + k], s_ii);
            s_ir = fmaf(ti[k], wr[j + k], s_ir);
            s_ri = fmaf(tr[k], wi[j + k], s_ri);
        }
        yr[j] = (s_rr - s_ii) + nrp[j] * scale;
        yi[j] = (s_ir + s_ri) + nip[j] * scale;
    }

    // ---- streaming stores (write-once data, evict-first): out[0]=real, out[1]=imag ----
    float4* outr = (float4*)(out + (size_t)b * NSAMP + n0);
    float4* outi = (float4*)(out + (size_t)BATCH * NSAMP + (size_t)b * NSAMP + n0);
    __stcs(outr + 0, make_float4(yr[0], yr[1], yr[2], yr[3]));
    __stcs(outr + 1, make_float4(yr[4], yr[5], yr[6], yr[7]));
    __stcs(outi + 0, make_float4(yi[0], yi[1], yi[2], yi[3]));
    __stcs(outi + 1, make_float4(yi[4], yi[5], yi[6], yi[7]));
}

extern "C" void kernel_launch(void* const* d_in, const int* in_sizes, int n_in,
                              void* d_out, int out_size)
{
    const float* x_real     = (const float*)d_in[0];
    const float* x_imag     = (const float*)d_in[1];
    const float* ebno_db    = (const float*)d_in[2];
    const float* cfo_u      = (const float*)d_in[3];
    const float* taps_real  = (const float*)d_in[4];
    const float* taps_imag  = (const float*)d_in[5];
    const float* noise_real = (const float*)d_in[6];
    const float* noise_imag = (const float*)d_in[7];
    float* out = (float*)d_out;

    dim3 grid(NSAMP / TILE, BATCH);   // (128, 64)
    wireless_channel_kernel<<<grid, NTHREADS>>>(
        x_real, x_imag, ebno_db, cfo_u, taps_real, taps_imag,
        noise_real, noise_imag, out);
}